// round 2
// baseline (speedup 1.0000x reference)
#include <cuda_runtime.h>
#include <math.h>
#include <stdint.h>

#define N_B 2
#define SEQ 2048      // LQ == LK
#define DM  1024
#define H   16
#define HD  64

// ---------------- scratch (no allocations allowed) ----------------
__device__ float g_Q[(size_t)N_B * H * SEQ * HD];
__device__ float g_K[(size_t)N_B * H * SEQ * HD];
__device__ float g_V[(size_t)N_B * H * SEQ * HD];
__device__ int   g_len[N_B];
__device__ float g_inv_scale[N_B];

// ---------------- kernel 0: valid-key counts from padding_mask ----------------
// Bool-dtype detection via the causal mask buffer (element [0][1] is True):
//   uint8  -> byte[1]==1
//   int32  -> byte[1]==0, byte[4]==1
//   float32-> byte[1]==0, byte[4]==0 (1.0f = 00 00 80 3F)
__global__ __launch_bounds__(256) void len_kernel(const unsigned char* __restrict__ mask,
                                                  const unsigned char* __restrict__ pm)
{
    __shared__ int cnt[N_B];
    __shared__ int dt;
    int t = threadIdx.x;
    if (t == 0) {
        if (mask[1] == 1)      dt = 0;   // uint8/bool
        else if (mask[4] == 1) dt = 1;   // int32
        else                   dt = 2;   // float32
    }
    if (t < N_B) cnt[t] = 0;
    __syncthreads();
    const int n = t / 128;               // 256 threads -> 128 per batch row
    const int dtype = dt;
    int local = 0;
    for (int k = (t & 127); k < SEQ; k += 128) {
        bool padded;
        if (dtype == 0)      padded = pm[n * SEQ + k] != 0;
        else if (dtype == 1) padded = ((const int*)pm)[n * SEQ + k] != 0;
        else                 padded = ((const float*)pm)[n * SEQ + k] != 0.0f;
        local += padded ? 0 : 1;
    }
    atomicAdd(&cnt[n], local);
    __syncthreads();
    if (t < N_B) {
        g_len[t] = cnt[t];
        g_inv_scale[t] = rsqrtf((float)cnt[t]);
    }
}

// ---------------- kernel 1: projection GEMM  C = X * W^T, head-split output ----
// X: [M=4096, 1024] row-major, W: [1024, 1024] row-major (out = x @ W^T)
// out[n][h][l][hd] with token m = n*2048 + l, channel o = h*64 + hd
__global__ __launch_bounds__(256) void proj_kernel(const float* __restrict__ X,
                                                   const float* __restrict__ W,
                                                   int sel)
{
    float* out = (sel == 0) ? g_Q : (sel == 1) ? g_K : g_V;

    __shared__ float As[8][132];
    __shared__ float Bs[8][132];

    const int tid = threadIdx.x;
    const int tx = tid & 15, ty = tid >> 4;
    const int m0 = blockIdx.y * 128;
    const int n0 = blockIdx.x * 128;
    const int lr  = tid >> 1;          // 0..127 tile row to load
    const int lk4 = (tid & 1) * 4;     // 0 or 4

    float acc[8][8] = {};

    const float* Aptr = X + (size_t)(m0 + lr) * DM + lk4;
    const float* Bptr = W + (size_t)(n0 + lr) * DM + lk4;

    for (int k0 = 0; k0 < DM; k0 += 8) {
        float4 a = *(const float4*)(Aptr + k0);
        float4 b = *(const float4*)(Bptr + k0);
        __syncthreads();
        As[lk4 + 0][lr] = a.x; As[lk4 + 1][lr] = a.y;
        As[lk4 + 2][lr] = a.z; As[lk4 + 3][lr] = a.w;
        Bs[lk4 + 0][lr] = b.x; Bs[lk4 + 1][lr] = b.y;
        Bs[lk4 + 2][lr] = b.z; Bs[lk4 + 3][lr] = b.w;
        __syncthreads();
#pragma unroll
        for (int kk = 0; kk < 8; kk++) {
            float af[8], bf[8];
            *(float4*)&af[0] = *(const float4*)&As[kk][ty * 8];
            *(float4*)&af[4] = *(const float4*)&As[kk][ty * 8 + 4];
            *(float4*)&bf[0] = *(const float4*)&Bs[kk][tx * 8];
            *(float4*)&bf[4] = *(const float4*)&Bs[kk][tx * 8 + 4];
#pragma unroll
            for (int i = 0; i < 8; i++)
#pragma unroll
                for (int j = 0; j < 8; j++)
                    acc[i][j] = fmaf(af[i], bf[j], acc[i][j]);
        }
    }

#pragma unroll
    for (int i = 0; i < 8; i++) {
        int m  = m0 + ty * 8 + i;
        int nb = m >> 11;          // / 2048
        int l  = m & 2047;
#pragma unroll
        for (int j4 = 0; j4 < 8; j4 += 4) {
            int o  = n0 + tx * 8 + j4;
            int hh = o >> 6;
            int hd = o & 63;
            float4 v = make_float4(acc[i][j4], acc[i][j4 + 1], acc[i][j4 + 2], acc[i][j4 + 3]);
            *(float4*)&out[(((size_t)(nb * H + hh)) * SEQ + l) * HD + hd] = v;
        }
    }
}

// ---------------- kernel 2: flash attention, 64x64 tiles, fp32 ---------------
#define SSTR 65
#define ATT_SMEM (3 * 64 * SSTR * 4)

__global__ __launch_bounds__(256) void attn_kernel(float* __restrict__ out)
{
    extern __shared__ float sm[];
    float* Qs = sm;                  // [64][65]
    float* KV = sm + 64 * SSTR;      // [64][65]  (K then V)
    float* Ps = sm + 2 * 64 * SSTR;  // [64][65]

    const int tid = threadIdx.x;
    const int tx = tid & 15, ty = tid >> 4;
    const int qt = blockIdx.x, hh = blockIdx.y, nb = blockIdx.z;
    const int q0 = qt * 64;

    const float* Qg = g_Q + ((size_t)(nb * H + hh) * SEQ + q0) * HD;
    const float* Kg = g_K + (size_t)(nb * H + hh) * SEQ * HD;
    const float* Vg = g_V + (size_t)(nb * H + hh) * SEQ * HD;

    const int   len  = g_len[nb];
    const float invs = g_inv_scale[nb];

    // load Q tile (64x64)
#pragma unroll
    for (int i = 0; i < 4; i++) {
        int id = tid + i * 256;
        int r = id >> 4, s4 = (id & 15) * 4;
        float4 v = *(const float4*)(Qg + r * HD + s4);
        Qs[r * SSTR + s4 + 0] = v.x; Qs[r * SSTR + s4 + 1] = v.y;
        Qs[r * SSTR + s4 + 2] = v.z; Qs[r * SSTR + s4 + 3] = v.w;
    }

    float m_i[4], l_i[4], oacc[4][4];
#pragma unroll
    for (int i = 0; i < 4; i++) {
        m_i[i] = -INFINITY; l_i[i] = 0.f;
#pragma unroll
        for (int c = 0; c < 4; c++) oacc[i][c] = 0.f;
    }

    int jend = qt;                         // causal: k0 <= q0+63
    int jl = (len + 63) / 64 - 1;          // padding: k0 < len
    if (jl < jend) jend = jl;

    for (int j = 0; j <= jend; j++) {
        const int k0 = j * 64;
        __syncthreads();
        // K tile
#pragma unroll
        for (int i = 0; i < 4; i++) {
            int id = tid + i * 256;
            int r = id >> 4, s4 = (id & 15) * 4;
            float4 v = *(const float4*)(Kg + (size_t)(k0 + r) * HD + s4);
            KV[r * SSTR + s4 + 0] = v.x; KV[r * SSTR + s4 + 1] = v.y;
            KV[r * SSTR + s4 + 2] = v.z; KV[r * SSTR + s4 + 3] = v.w;
        }
        __syncthreads();

        // S = Q * K^T  (4x4 per thread)
        float s[4][4] = {};
#pragma unroll 8
        for (int kd = 0; kd < 64; kd++) {
            float a0 = Qs[(ty * 4 + 0) * SSTR + kd];
            float a1 = Qs[(ty * 4 + 1) * SSTR + kd];
            float a2 = Qs[(ty * 4 + 2) * SSTR + kd];
            float a3 = Qs[(ty * 4 + 3) * SSTR + kd];
            float b0 = KV[(tx * 4 + 0) * SSTR + kd];
            float b1 = KV[(tx * 4 + 1) * SSTR + kd];
            float b2 = KV[(tx * 4 + 2) * SSTR + kd];
            float b3 = KV[(tx * 4 + 3) * SSTR + kd];
            s[0][0] = fmaf(a0, b0, s[0][0]); s[0][1] = fmaf(a0, b1, s[0][1]);
            s[0][2] = fmaf(a0, b2, s[0][2]); s[0][3] = fmaf(a0, b3, s[0][3]);
            s[1][0] = fmaf(a1, b0, s[1][0]); s[1][1] = fmaf(a1, b1, s[1][1]);
            s[1][2] = fmaf(a1, b2, s[1][2]); s[1][3] = fmaf(a1, b3, s[1][3]);
            s[2][0] = fmaf(a2, b0, s[2][0]); s[2][1] = fmaf(a2, b1, s[2][1]);
            s[2][2] = fmaf(a2, b2, s[2][2]); s[2][3] = fmaf(a2, b3, s[2][3]);
            s[3][0] = fmaf(a3, b0, s[3][0]); s[3][1] = fmaf(a3, b1, s[3][1]);
            s[3][2] = fmaf(a3, b2, s[3][2]); s[3][3] = fmaf(a3, b3, s[3][3]);
        }

        // mask + online softmax (row stats across the 16 tx lanes, same half-warp)
#pragma unroll
        for (int i = 0; i < 4; i++) {
            int q = q0 + ty * 4 + i;
            float mx = -INFINITY;
#pragma unroll
            for (int c = 0; c < 4; c++) {
                int k = k0 + tx * 4 + c;
                float sv = (k > q || k >= len) ? -INFINITY : s[i][c] * invs;
                s[i][c] = sv;
                mx = fmaxf(mx, sv);
            }
            mx = fmaxf(mx, __shfl_xor_sync(0xffffffffu, mx, 1));
            mx = fmaxf(mx, __shfl_xor_sync(0xffffffffu, mx, 2));
            mx = fmaxf(mx, __shfl_xor_sync(0xffffffffu, mx, 4));
            mx = fmaxf(mx, __shfl_xor_sync(0xffffffffu, mx, 8));

            float m_new = fmaxf(m_i[i], mx);          // finite: tile j=0 has k=0 valid
            float alpha = __expf(m_i[i] - m_new);
            float rs = 0.f;
#pragma unroll
            for (int c = 0; c < 4; c++) {
                float p = __expf(s[i][c] - m_new);
                s[i][c] = p;
                rs += p;
            }
            rs += __shfl_xor_sync(0xffffffffu, rs, 1);
            rs += __shfl_xor_sync(0xffffffffu, rs, 2);
            rs += __shfl_xor_sync(0xffffffffu, rs, 4);
            rs += __shfl_xor_sync(0xffffffffu, rs, 8);

            l_i[i] = l_i[i] * alpha + rs;
            m_i[i] = m_new;
#pragma unroll
            for (int c = 0; c < 4; c++) oacc[i][c] *= alpha;
#pragma unroll
            for (int c = 0; c < 4; c++)
                Ps[(ty * 4 + i) * SSTR + tx * 4 + c] = s[i][c];
        }
        __syncthreads();   // Ps ready; K reads done -> safe to overwrite KV with V

        // V tile
#pragma unroll
        for (int i = 0; i < 4; i++) {
            int id = tid + i * 256;
            int r = id >> 4, s4 = (id & 15) * 4;
            float4 v = *(const float4*)(Vg + (size_t)(k0 + r) * HD + s4);
            KV[r * SSTR + s4 + 0] = v.x; KV[r * SSTR + s4 + 1] = v.y;
            KV[r * SSTR + s4 + 2] = v.z; KV[r * SSTR + s4 + 3] = v.w;
        }
        __syncthreads();

        // O += P * V
#pragma unroll 8
        for (int kd = 0; kd < 64; kd++) {
            float a0 = Ps[(ty * 4 + 0) * SSTR + kd];
            float a1 = Ps[(ty * 4 + 1) * SSTR + kd];
            float a2 = Ps[(ty * 4 + 2) * SSTR + kd];
            float a3 = Ps[(ty * 4 + 3) * SSTR + kd];
            float b0 = KV[kd * SSTR + tx * 4 + 0];
            float b1 = KV[kd * SSTR + tx * 4 + 1];
            float b2 = KV[kd * SSTR + tx * 4 + 2];
            float b3 = KV[kd * SSTR + tx * 4 + 3];
            oacc[0][0] = fmaf(a0, b0, oacc[0][0]); oacc[0][1] = fmaf(a0, b1, oacc[0][1]);
            oacc[0][2] = fmaf(a0, b2, oacc[0][2]); oacc[0][3] = fmaf(a0, b3, oacc[0][3]);
            oacc[1][0] = fmaf(a1, b0, oacc[1][0]); oacc[1][1] = fmaf(a1, b1, oacc[1][1]);
            oacc[1][2] = fmaf(a1, b2, oacc[1][2]); oacc[1][3] = fmaf(a1, b3, oacc[1][3]);
            oacc[2][0] = fmaf(a2, b0, oacc[2][0]); oacc[2][1] = fmaf(a2, b1, oacc[2][1]);
            oacc[2][2] = fmaf(a2, b2, oacc[2][2]); oacc[2][3] = fmaf(a2, b3, oacc[2][3]);
            oacc[3][0] = fmaf(a3, b0, oacc[3][0]); oacc[3][1] = fmaf(a3, b1, oacc[3][1]);
            oacc[3][2] = fmaf(a3, b2, oacc[3][2]); oacc[3][3] = fmaf(a3, b3, oacc[3][3]);
        }
    }

    // epilogue: O / l, write (n, lq, h*64 + d)
#pragma unroll
    for (int i = 0; i < 4; i++) {
        float il = 1.f / l_i[i];
        int q = q0 + ty * 4 + i;
        float4 v = make_float4(oacc[i][0] * il, oacc[i][1] * il,
                               oacc[i][2] * il, oacc[i][3] * il);
        *(float4*)&out[((size_t)nb * SEQ + q) * DM + hh * HD + tx * 4] = v;
    }
}

// ---------------- launch ----------------
extern "C" void kernel_launch(void* const* d_in, const int* in_sizes, int n_in,
                              void* d_out, int out_size)
{
    const float* query = (const float*)d_in[0];
    const float* key   = (const float*)d_in[1];
    const float* Wq    = (const float*)d_in[2];
    const float* Wk    = (const float*)d_in[3];
    const float* Wv    = (const float*)d_in[4];
    const unsigned char* mask = (const unsigned char*)d_in[5];
    const unsigned char* pm   = (const unsigned char*)d_in[6];
    float* out = (float*)d_out;

    cudaFuncSetAttribute(attn_kernel, cudaFuncAttributeMaxDynamicSharedMemorySize, ATT_SMEM);

    len_kernel<<<1, 256>>>(mask, pm);

    dim3 pg(DM / 128, (N_B * SEQ) / 128);
    proj_kernel<<<pg, 256>>>(query, Wq, 0);
    proj_kernel<<<pg, 256>>>(key,   Wk, 1);
    proj_kernel<<<pg, 256>>>(key,   Wv, 2);

    attn_kernel<<<dim3(SEQ / 64, H, N_B), 256, ATT_SMEM>>>(out);
}

// round 4
// speedup vs baseline: 1.3710x; 1.3710x over previous
#include <cuda_runtime.h>
#include <cuda_bf16.h>
#include <math.h>
#include <stdint.h>

#define N_B 2
#define SEQ 2048      // LQ == LK
#define DM  1024
#define H   16
#define HD  64

// ---------------- scratch (no allocations allowed) ----------------
__device__ float g_Q[(size_t)N_B * H * SEQ * HD];
__device__ float g_K[(size_t)N_B * H * SEQ * HD];
__device__ float g_V[(size_t)N_B * H * SEQ * HD];
__device__ int   g_len[N_B];
__device__ float g_inv_scale[N_B];

// ---------------- kernel 0: valid-key counts from padding_mask ----------------
__global__ __launch_bounds__(256) void len_kernel(const unsigned char* __restrict__ mask,
                                                  const unsigned char* __restrict__ pm)
{
    __shared__ int cnt[N_B];
    __shared__ int dt;
    int t = threadIdx.x;
    if (t == 0) {
        if (mask[1] == 1)      dt = 0;   // uint8/bool
        else if (mask[4] == 1) dt = 1;   // int32
        else                   dt = 2;   // float32
    }
    if (t < N_B) cnt[t] = 0;
    __syncthreads();
    const int n = t / 128;
    const int dtype = dt;
    int local = 0;
    for (int k = (t & 127); k < SEQ; k += 128) {
        bool padded;
        if (dtype == 0)      padded = pm[n * SEQ + k] != 0;
        else if (dtype == 1) padded = ((const int*)pm)[n * SEQ + k] != 0;
        else                 padded = ((const float*)pm)[n * SEQ + k] != 0.0f;
        local += padded ? 0 : 1;
    }
    atomicAdd(&cnt[n], local);
    __syncthreads();
    if (t < N_B) {
        g_len[t] = cnt[t];
        g_inv_scale[t] = rsqrtf((float)cnt[t]);
    }
}

// ---------------- mma.sync helpers ----------------
__device__ __forceinline__ void mma_bf16(float* c, const uint32_t* a, const uint32_t* b)
{
    asm volatile(
        "mma.sync.aligned.m16n8k16.row.col.f32.bf16.bf16.f32 "
        "{%0,%1,%2,%3}, {%4,%5,%6,%7}, {%8,%9}, {%0,%1,%2,%3};"
        : "+f"(c[0]), "+f"(c[1]), "+f"(c[2]), "+f"(c[3])
        : "r"(a[0]), "r"(a[1]), "r"(a[2]), "r"(a[3]), "r"(b[0]), "r"(b[1]));
}

__device__ __forceinline__ void split2(float x, float y, uint32_t& hi, uint32_t& lo)
{
    __nv_bfloat16 hx = __float2bfloat16_rn(x);
    __nv_bfloat16 hy = __float2bfloat16_rn(y);
    __nv_bfloat16 lx = __float2bfloat16_rn(x - __bfloat162float(hx));
    __nv_bfloat16 ly = __float2bfloat16_rn(y - __bfloat162float(hy));
    hi = ((uint32_t)__bfloat16_as_ushort(hy) << 16) | __bfloat16_as_ushort(hx);
    lo = ((uint32_t)__bfloat16_as_ushort(ly) << 16) | __bfloat16_as_ushort(lx);
}

// ---------------- kernel 1: bf16x3 mma.sync projection GEMM ----------------
// C[4096,1024] = X @ W^T, head-split output layout.
// Block 128x128, BK=32, 8 warps as 2(m) x 4(n), warp tile 64x32.
#define PBM 128
#define PBN 128
#define PBK 32
#define PSTR 20          // row stride in uint32 (40 bf16 = 80B): conflict-free

__global__ __launch_bounds__(256, 2) void proj_mma(const float* __restrict__ X,
                                                   const float* __restrict__ W,
                                                   int sel)
{
    float* out = (sel == 0) ? g_Q : (sel == 1) ? g_K : g_V;

    __shared__ __align__(16) uint32_t sAhi[PBM * PSTR];
    __shared__ __align__(16) uint32_t sAlo[PBM * PSTR];
    __shared__ __align__(16) uint32_t sBhi[PBN * PSTR];
    __shared__ __align__(16) uint32_t sBlo[PBN * PSTR];

    const int tid  = threadIdx.x;
    const int lane = tid & 31, wid = tid >> 5;
    const int wm = (wid >> 2) * 64;      // warp m offset in tile
    const int wn = (wid & 3) * 32;       // warp n offset in tile
    const int grp = lane >> 2;           // 0..7
    const int qk  = lane & 3;            // k pair index

    const int bm0 = blockIdx.y * PBM;
    const int bn0 = blockIdx.x * PBN;

    float acc[4][4][4];
#pragma unroll
    for (int i = 0; i < 4; i++)
#pragma unroll
        for (int j = 0; j < 4; j++)
#pragma unroll
            for (int r = 0; r < 4; r++) acc[i][j][r] = 0.f;

    const int lr  = tid >> 3;            // 0..31 (row within pass)
    const int lc4 = (tid & 7) * 4;       // k column (floats)

    for (int kt = 0; kt < DM / PBK; kt++) {
        const int kbase = kt * PBK;
        __syncthreads();
        // load + split A tile (128 x 32) and B tile (128 x 32)
#pragma unroll
        for (int p = 0; p < 4; p++) {
            int r = lr + p * 32;
            float4 va = *(const float4*)(X + (size_t)(bm0 + r) * DM + kbase + lc4);
            uint32_t h0, l0, h1, l1;
            split2(va.x, va.y, h0, l0);
            split2(va.z, va.w, h1, l1);
            sAhi[r * PSTR + lc4 / 2]     = h0;
            sAhi[r * PSTR + lc4 / 2 + 1] = h1;
            sAlo[r * PSTR + lc4 / 2]     = l0;
            sAlo[r * PSTR + lc4 / 2 + 1] = l1;
            float4 vb = *(const float4*)(W + (size_t)(bn0 + r) * DM + kbase + lc4);
            split2(vb.x, vb.y, h0, l0);
            split2(vb.z, vb.w, h1, l1);
            sBhi[r * PSTR + lc4 / 2]     = h0;
            sBhi[r * PSTR + lc4 / 2 + 1] = h1;
            sBlo[r * PSTR + lc4 / 2]     = l0;
            sBlo[r * PSTR + lc4 / 2 + 1] = l1;
        }
        __syncthreads();

#pragma unroll
        for (int ks = 0; ks < 2; ks++) {         // two k16 halves
            const int koff = ks * 8 + qk;
            uint32_t ah[4][4], al[4][4];
#pragma unroll
            for (int i = 0; i < 4; i++) {
                int row = (wm + i * 16 + grp) * PSTR;
                ah[i][0] = sAhi[row + koff];
                ah[i][1] = sAhi[row + 8 * PSTR + koff];
                ah[i][2] = sAhi[row + koff + 4];
                ah[i][3] = sAhi[row + 8 * PSTR + koff + 4];
                al[i][0] = sAlo[row + koff];
                al[i][1] = sAlo[row + 8 * PSTR + koff];
                al[i][2] = sAlo[row + koff + 4];
                al[i][3] = sAlo[row + 8 * PSTR + koff + 4];
            }
#pragma unroll
            for (int j = 0; j < 4; j++) {
                int nrow = (wn + j * 8 + grp) * PSTR;
                uint32_t bh[2], bl[2];
                bh[0] = sBhi[nrow + koff];
                bh[1] = sBhi[nrow + koff + 4];
                bl[0] = sBlo[nrow + koff];
                bl[1] = sBlo[nrow + koff + 4];
#pragma unroll
                for (int i = 0; i < 4; i++) mma_bf16(acc[i][j], ah[i], bh);
#pragma unroll
                for (int i = 0; i < 4; i++) mma_bf16(acc[i][j], ah[i], bl);
#pragma unroll
                for (int i = 0; i < 4; i++) mma_bf16(acc[i][j], al[i], bh);
            }
        }
    }

    // epilogue: head-split writes (float2 per c-pair)
#pragma unroll
    for (int i = 0; i < 4; i++) {
        int m0r = bm0 + wm + i * 16 + grp;
#pragma unroll
        for (int j = 0; j < 4; j++) {
            int o = bn0 + wn + j * 8 + qk * 2;
            int hh = o >> 6, hd = o & 63;
#pragma unroll
            for (int half = 0; half < 2; half++) {
                int m = m0r + half * 8;
                int nb = m >> 11, l = m & 2047;
                float2 v = make_float2(acc[i][j][half * 2], acc[i][j][half * 2 + 1]);
                *(float2*)&out[(((size_t)(nb * H + hh)) * SEQ + l) * HD + hd] = v;
            }
        }
    }
}

// ---------------- kernel 2: flash attention, 64x64 tiles, fp32 ---------------
#define SSTR 65
#define ATT_SMEM (3 * 64 * SSTR * 4)

__global__ __launch_bounds__(256) void attn_kernel(float* __restrict__ out)
{
    extern __shared__ float sm[];
    float* Qs = sm;                  // [64][65]
    float* KV = sm + 64 * SSTR;      // [64][65]  (K then V)
    float* Ps = sm + 2 * 64 * SSTR;  // [64][65]

    const int tid = threadIdx.x;
    const int tx = tid & 15, ty = tid >> 4;
    const int qt = blockIdx.x, hh = blockIdx.y, nb = blockIdx.z;
    const int q0 = qt * 64;

    const float* Qg = g_Q + ((size_t)(nb * H + hh) * SEQ + q0) * HD;
    const float* Kg = g_K + (size_t)(nb * H + hh) * SEQ * HD;
    const float* Vg = g_V + (size_t)(nb * H + hh) * SEQ * HD;

    const int   len  = g_len[nb];
    const float invs = g_inv_scale[nb];

#pragma unroll
    for (int i = 0; i < 4; i++) {
        int id = tid + i * 256;
        int r = id >> 4, s4 = (id & 15) * 4;
        float4 v = *(const float4*)(Qg + r * HD + s4);
        Qs[r * SSTR + s4 + 0] = v.x; Qs[r * SSTR + s4 + 1] = v.y;
        Qs[r * SSTR + s4 + 2] = v.z; Qs[r * SSTR + s4 + 3] = v.w;
    }

    float m_i[4], l_i[4], oacc[4][4];
#pragma unroll
    for (int i = 0; i < 4; i++) {
        m_i[i] = -INFINITY; l_i[i] = 0.f;
#pragma unroll
        for (int c = 0; c < 4; c++) oacc[i][c] = 0.f;
    }

    int jend = qt;
    int jl = (len + 63) / 64 - 1;
    if (jl < jend) jend = jl;

    for (int j = 0; j <= jend; j++) {
        const int k0 = j * 64;
        __syncthreads();
#pragma unroll
        for (int i = 0; i < 4; i++) {
            int id = tid + i * 256;
            int r = id >> 4, s4 = (id & 15) * 4;
            float4 v = *(const float4*)(Kg + (size_t)(k0 + r) * HD + s4);
            KV[r * SSTR + s4 + 0] = v.x; KV[r * SSTR + s4 + 1] = v.y;
            KV[r * SSTR + s4 + 2] = v.z; KV[r * SSTR + s4 + 3] = v.w;
        }
        __syncthreads();

        float s[4][4] = {};
#pragma unroll 8
        for (int kd = 0; kd < 64; kd++) {
            float a0 = Qs[(ty * 4 + 0) * SSTR + kd];
            float a1 = Qs[(ty * 4 + 1) * SSTR + kd];
            float a2 = Qs[(ty * 4 + 2) * SSTR + kd];
            float a3 = Qs[(ty * 4 + 3) * SSTR + kd];
            float b0 = KV[(tx * 4 + 0) * SSTR + kd];
            float b1 = KV[(tx * 4 + 1) * SSTR + kd];
            float b2 = KV[(tx * 4 + 2) * SSTR + kd];
            float b3 = KV[(tx * 4 + 3) * SSTR + kd];
            s[0][0] = fmaf(a0, b0, s[0][0]); s[0][1] = fmaf(a0, b1, s[0][1]);
            s[0][2] = fmaf(a0, b2, s[0][2]); s[0][3] = fmaf(a0, b3, s[0][3]);
            s[1][0] = fmaf(a1, b0, s[1][0]); s[1][1] = fmaf(a1, b1, s[1][1]);
            s[1][2] = fmaf(a1, b2, s[1][2]); s[1][3] = fmaf(a1, b3, s[1][3]);
            s[2][0] = fmaf(a2, b0, s[2][0]); s[2][1] = fmaf(a2, b1, s[2][1]);
            s[2][2] = fmaf(a2, b2, s[2][2]); s[2][3] = fmaf(a2, b3, s[2][3]);
            s[3][0] = fmaf(a3, b0, s[3][0]); s[3][1] = fmaf(a3, b1, s[3][1]);
            s[3][2] = fmaf(a3, b2, s[3][2]); s[3][3] = fmaf(a3, b3, s[3][3]);
        }

#pragma unroll
        for (int i = 0; i < 4; i++) {
            int q = q0 + ty * 4 + i;
            float mx = -INFINITY;
#pragma unroll
            for (int c = 0; c < 4; c++) {
                int k = k0 + tx * 4 + c;
                float sv = (k > q || k >= len) ? -INFINITY : s[i][c] * invs;
                s[i][c] = sv;
                mx = fmaxf(mx, sv);
            }
            mx = fmaxf(mx, __shfl_xor_sync(0xffffffffu, mx, 1));
            mx = fmaxf(mx, __shfl_xor_sync(0xffffffffu, mx, 2));
            mx = fmaxf(mx, __shfl_xor_sync(0xffffffffu, mx, 4));
            mx = fmaxf(mx, __shfl_xor_sync(0xffffffffu, mx, 8));

            float m_new = fmaxf(m_i[i], mx);
            float alpha = __expf(m_i[i] - m_new);
            float rs = 0.f;
#pragma unroll
            for (int c = 0; c < 4; c++) {
                float p = __expf(s[i][c] - m_new);
                s[i][c] = p;
                rs += p;
            }
            rs += __shfl_xor_sync(0xffffffffu, rs, 1);
            rs += __shfl_xor_sync(0xffffffffu, rs, 2);
            rs += __shfl_xor_sync(0xffffffffu, rs, 4);
            rs += __shfl_xor_sync(0xffffffffu, rs, 8);

            l_i[i] = l_i[i] * alpha + rs;
            m_i[i] = m_new;
#pragma unroll
            for (int c = 0; c < 4; c++) oacc[i][c] *= alpha;
#pragma unroll
            for (int c = 0; c < 4; c++)
                Ps[(ty * 4 + i) * SSTR + tx * 4 + c] = s[i][c];
        }
        __syncthreads();

#pragma unroll
        for (int i = 0; i < 4; i++) {
            int id = tid + i * 256;
            int r = id >> 4, s4 = (id & 15) * 4;
            float4 v = *(const float4*)(Vg + (size_t)(k0 + r) * HD + s4);
            KV[r * SSTR + s4 + 0] = v.x; KV[r * SSTR + s4 + 1] = v.y;
            KV[r * SSTR + s4 + 2] = v.z; KV[r * SSTR + s4 + 3] = v.w;
        }
        __syncthreads();

#pragma unroll 8
        for (int kd = 0; kd < 64; kd++) {
            float a0 = Ps[(ty * 4 + 0) * SSTR + kd];
            float a1 = Ps[(ty * 4 + 1) * SSTR + kd];
            float a2 = Ps[(ty * 4 + 2) * SSTR + kd];
            float a3 = Ps[(ty * 4 + 3) * SSTR + kd];
            float b0 = KV[kd * SSTR + tx * 4 + 0];
            float b1 = KV[kd * SSTR + tx * 4 + 1];
            float b2 = KV[kd * SSTR + tx * 4 + 2];
            float b3 = KV[kd * SSTR + tx * 4 + 3];
            oacc[0][0] = fmaf(a0, b0, oacc[0][0]); oacc[0][1] = fmaf(a0, b1, oacc[0][1]);
            oacc[0][2] = fmaf(a0, b2, oacc[0][2]); oacc[0][3] = fmaf(a0, b3, oacc[0][3]);
            oacc[1][0] = fmaf(a1, b0, oacc[1][0]); oacc[1][1] = fmaf(a1, b1, oacc[1][1]);
            oacc[1][2] = fmaf(a1, b2, oacc[1][2]); oacc[1][3] = fmaf(a1, b3, oacc[1][3]);
            oacc[2][0] = fmaf(a2, b0, oacc[2][0]); oacc[2][1] = fmaf(a2, b1, oacc[2][1]);
            oacc[2][2] = fmaf(a2, b2, oacc[2][2]); oacc[2][3] = fmaf(a2, b3, oacc[2][3]);
            oacc[3][0] = fmaf(a3, b0, oacc[3][0]); oacc[3][1] = fmaf(a3, b1, oacc[3][1]);
            oacc[3][2] = fmaf(a3, b2, oacc[3][2]); oacc[3][3] = fmaf(a3, b3, oacc[3][3]);
        }
    }

#pragma unroll
    for (int i = 0; i < 4; i++) {
        float il = 1.f / l_i[i];
        int q = q0 + ty * 4 + i;
        float4 v = make_float4(oacc[i][0] * il, oacc[i][1] * il,
                               oacc[i][2] * il, oacc[i][3] * il);
        *(float4*)&out[((size_t)nb * SEQ + q) * DM + hh * HD + tx * 4] = v;
    }
}

// ---------------- launch ----------------
extern "C" void kernel_launch(void* const* d_in, const int* in_sizes, int n_in,
                              void* d_out, int out_size)
{
    const float* query = (const float*)d_in[0];
    const float* key   = (const float*)d_in[1];
    const float* Wq    = (const float*)d_in[2];
    const float* Wk    = (const float*)d_in[3];
    const float* Wv    = (const float*)d_in[4];
    const unsigned char* mask = (const unsigned char*)d_in[5];
    const unsigned char* pm   = (const unsigned char*)d_in[6];
    float* out = (float*)d_out;

    cudaFuncSetAttribute(attn_kernel, cudaFuncAttributeMaxDynamicSharedMemorySize, ATT_SMEM);

    len_kernel<<<1, 256>>>(mask, pm);

    dim3 pg(DM / PBN, (N_B * SEQ) / PBM);      // (8, 32)
    proj_mma<<<pg, 256>>>(query, Wq, 0);
    proj_mma<<<pg, 256>>>(key,   Wk, 1);
    proj_mma<<<pg, 256>>>(key,   Wv, 2);

    attn_kernel<<<dim3(SEQ / 64, H, N_B), 256, ATT_SMEM>>>(out);
}

// round 5
// speedup vs baseline: 2.1343x; 1.5568x over previous
#include <cuda_runtime.h>
#include <cuda_bf16.h>
#include <math.h>
#include <stdint.h>

#define N_B 2
#define SEQ 2048      // LQ == LK
#define DM  1024
#define H   16
#define HD  64

// ---------------- scratch: Q/K/V as packed bf16 hi/lo (u32 = 2 adjacent d) ----
// layout: [n][h][token][d/2]  (32 u32 per token per head)
#define TOKENS ((size_t)N_B * H * SEQ)
__device__ uint32_t g_Qhi[TOKENS * 32], g_Qlo[TOKENS * 32];
__device__ uint32_t g_Khi[TOKENS * 32], g_Klo[TOKENS * 32];
__device__ uint32_t g_Vhi[TOKENS * 32], g_Vlo[TOKENS * 32];
__device__ int   g_len[N_B];
__device__ float g_inv_scale[N_B];

// ---------------- kernel 0: valid-key counts from padding_mask ----------------
__global__ __launch_bounds__(256) void len_kernel(const unsigned char* __restrict__ mask,
                                                  const unsigned char* __restrict__ pm)
{
    __shared__ int cnt[N_B];
    __shared__ int dt;
    int t = threadIdx.x;
    if (t == 0) {
        if (mask[1] == 1)      dt = 0;   // uint8/bool
        else if (mask[4] == 1) dt = 1;   // int32
        else                   dt = 2;   // float32
    }
    if (t < N_B) cnt[t] = 0;
    __syncthreads();
    const int n = t / 128;
    const int dtype = dt;
    int local = 0;
    for (int k = (t & 127); k < SEQ; k += 128) {
        bool padded;
        if (dtype == 0)      padded = pm[n * SEQ + k] != 0;
        else if (dtype == 1) padded = ((const int*)pm)[n * SEQ + k] != 0;
        else                 padded = ((const float*)pm)[n * SEQ + k] != 0.0f;
        local += padded ? 0 : 1;
    }
    atomicAdd(&cnt[n], local);
    __syncthreads();
    if (t < N_B) {
        g_len[t] = cnt[t];
        g_inv_scale[t] = rsqrtf((float)cnt[t]);
    }
}

// ---------------- mma.sync helpers ----------------
__device__ __forceinline__ void mma_bf16(float* c, const uint32_t* a, const uint32_t* b)
{
    asm volatile(
        "mma.sync.aligned.m16n8k16.row.col.f32.bf16.bf16.f32 "
        "{%0,%1,%2,%3}, {%4,%5,%6,%7}, {%8,%9}, {%0,%1,%2,%3};"
        : "+f"(c[0]), "+f"(c[1]), "+f"(c[2]), "+f"(c[3])
        : "r"(a[0]), "r"(a[1]), "r"(a[2]), "r"(a[3]), "r"(b[0]), "r"(b[1]));
}

__device__ __forceinline__ void split2(float x, float y, uint32_t& hi, uint32_t& lo)
{
    __nv_bfloat16 hx = __float2bfloat16_rn(x);
    __nv_bfloat16 hy = __float2bfloat16_rn(y);
    __nv_bfloat16 lx = __float2bfloat16_rn(x - __bfloat162float(hx));
    __nv_bfloat16 ly = __float2bfloat16_rn(y - __bfloat162float(hy));
    hi = ((uint32_t)__bfloat16_as_ushort(hy) << 16) | __bfloat16_as_ushort(hx);
    lo = ((uint32_t)__bfloat16_as_ushort(ly) << 16) | __bfloat16_as_ushort(lx);
}

// ---------------- kernel 1: bf16x3 mma.sync projection GEMM ----------------
#define PBM 128
#define PBN 128
#define PBK 32
#define PSTR 20

__global__ __launch_bounds__(256, 2) void proj_mma(const float* __restrict__ X,
                                                   const float* __restrict__ W,
                                                   int sel)
{
    uint32_t* outhi = (sel == 0) ? g_Qhi : (sel == 1) ? g_Khi : g_Vhi;
    uint32_t* outlo = (sel == 0) ? g_Qlo : (sel == 1) ? g_Klo : g_Vlo;

    __shared__ __align__(16) uint32_t sAhi[PBM * PSTR];
    __shared__ __align__(16) uint32_t sAlo[PBM * PSTR];
    __shared__ __align__(16) uint32_t sBhi[PBN * PSTR];
    __shared__ __align__(16) uint32_t sBlo[PBN * PSTR];

    const int tid  = threadIdx.x;
    const int lane = tid & 31, wid = tid >> 5;
    const int wm = (wid >> 2) * 64;
    const int wn = (wid & 3) * 32;
    const int grp = lane >> 2;
    const int qk  = lane & 3;

    const int bm0 = blockIdx.y * PBM;
    const int bn0 = blockIdx.x * PBN;

    float acc[4][4][4];
#pragma unroll
    for (int i = 0; i < 4; i++)
#pragma unroll
        for (int j = 0; j < 4; j++)
#pragma unroll
            for (int r = 0; r < 4; r++) acc[i][j][r] = 0.f;

    const int lr  = tid >> 3;
    const int lc4 = (tid & 7) * 4;

    for (int kt = 0; kt < DM / PBK; kt++) {
        const int kbase = kt * PBK;
        __syncthreads();
#pragma unroll
        for (int p = 0; p < 4; p++) {
            int r = lr + p * 32;
            float4 va = *(const float4*)(X + (size_t)(bm0 + r) * DM + kbase + lc4);
            uint32_t h0, l0, h1, l1;
            split2(va.x, va.y, h0, l0);
            split2(va.z, va.w, h1, l1);
            sAhi[r * PSTR + lc4 / 2]     = h0;
            sAhi[r * PSTR + lc4 / 2 + 1] = h1;
            sAlo[r * PSTR + lc4 / 2]     = l0;
            sAlo[r * PSTR + lc4 / 2 + 1] = l1;
            float4 vb = *(const float4*)(W + (size_t)(bn0 + r) * DM + kbase + lc4);
            split2(vb.x, vb.y, h0, l0);
            split2(vb.z, vb.w, h1, l1);
            sBhi[r * PSTR + lc4 / 2]     = h0;
            sBhi[r * PSTR + lc4 / 2 + 1] = h1;
            sBlo[r * PSTR + lc4 / 2]     = l0;
            sBlo[r * PSTR + lc4 / 2 + 1] = l1;
        }
        __syncthreads();

#pragma unroll
        for (int ks = 0; ks < 2; ks++) {
            const int koff = ks * 8 + qk;
            uint32_t ah[4][4], al[4][4];
#pragma unroll
            for (int i = 0; i < 4; i++) {
                int row = (wm + i * 16 + grp) * PSTR;
                ah[i][0] = sAhi[row + koff];
                ah[i][1] = sAhi[row + 8 * PSTR + koff];
                ah[i][2] = sAhi[row + koff + 4];
                ah[i][3] = sAhi[row + 8 * PSTR + koff + 4];
                al[i][0] = sAlo[row + koff];
                al[i][1] = sAlo[row + 8 * PSTR + koff];
                al[i][2] = sAlo[row + koff + 4];
                al[i][3] = sAlo[row + 8 * PSTR + koff + 4];
            }
#pragma unroll
            for (int j = 0; j < 4; j++) {
                int nrow = (wn + j * 8 + grp) * PSTR;
                uint32_t bh[2], bl[2];
                bh[0] = sBhi[nrow + koff];
                bh[1] = sBhi[nrow + koff + 4];
                bl[0] = sBlo[nrow + koff];
                bl[1] = sBlo[nrow + koff + 4];
#pragma unroll
                for (int i = 0; i < 4; i++) mma_bf16(acc[i][j], ah[i], bh);
#pragma unroll
                for (int i = 0; i < 4; i++) mma_bf16(acc[i][j], ah[i], bl);
#pragma unroll
                for (int i = 0; i < 4; i++) mma_bf16(acc[i][j], al[i], bh);
            }
        }
    }

    // epilogue: split to bf16 hi/lo, head-split layout [n][h][l][d/2]
#pragma unroll
    for (int i = 0; i < 4; i++) {
        int m0r = bm0 + wm + i * 16 + grp;
#pragma unroll
        for (int j = 0; j < 4; j++) {
            int o  = bn0 + wn + j * 8 + qk * 2;
            int hh = o >> 6, hd = o & 63;
#pragma unroll
            for (int half = 0; half < 2; half++) {
                int m = m0r + half * 8;
                int nb = m >> 11, l = m & 2047;
                uint32_t hi, lo;
                split2(acc[i][j][half * 2], acc[i][j][half * 2 + 1], hi, lo);
                size_t base = ((size_t)(nb * H + hh) * SEQ + l) * 32 + (hd >> 1);
                outhi[base] = hi;
                outlo[base] = lo;
            }
        }
    }
}

// ---------------- kernel 2: mma.sync flash attention -------------------------
// CTA: 128 q rows, 8 warps x 16 rows; key tiles of 64.
#define KSTR 36   // smem row stride in u32 (64 elems = 32 u32 + pad 4)

__global__ __launch_bounds__(256) void attn_mma(float* __restrict__ out)
{
    __shared__ uint32_t sKhi[64 * KSTR], sKlo[64 * KSTR];   // [key][d/2]
    __shared__ uint32_t sVhi[64 * KSTR], sVlo[64 * KSTR];   // [d][key/2] (transposed)

    const int tid  = threadIdx.x;
    const int lane = tid & 31, w = tid >> 5;
    const int grp = lane >> 2;
    const int qk  = lane & 3;

    const int qt = blockIdx.x, hh = blockIdx.y, nb = blockIdx.z;
    const int q0 = qt * 128;
    const int q0w = q0 + w * 16;

    const size_t headbase = (size_t)(nb * H + hh) * SEQ;
    const int   len  = g_len[nb];
    const float invs = g_inv_scale[nb];

    // ---- Q fragments, register-resident for entire kernel ----
    uint32_t aQhi[4][4], aQlo[4][4];
    {
        const uint32_t* Qh = g_Qhi + (headbase + q0w) * 32;
        const uint32_t* Ql = g_Qlo + (headbase + q0w) * 32;
#pragma unroll
        for (int sk = 0; sk < 4; sk++) {
            int o = sk * 8 + qk;
            aQhi[sk][0] = Qh[grp * 32 + o];
            aQhi[sk][1] = Qh[(grp + 8) * 32 + o];
            aQhi[sk][2] = Qh[grp * 32 + o + 4];
            aQhi[sk][3] = Qh[(grp + 8) * 32 + o + 4];
            aQlo[sk][0] = Ql[grp * 32 + o];
            aQlo[sk][1] = Ql[(grp + 8) * 32 + o];
            aQlo[sk][2] = Ql[grp * 32 + o + 4];
            aQlo[sk][3] = Ql[(grp + 8) * 32 + o + 4];
        }
    }

    float oacc[8][4];
#pragma unroll
    for (int j = 0; j < 8; j++)
#pragma unroll
        for (int c = 0; c < 4; c++) oacc[j][c] = 0.f;
    float m0 = -INFINITY, m1 = -INFINITY, l0 = 0.f, l1 = 0.f;

    const int qrow0 = q0w + grp;
    const int qrow1 = qrow0 + 8;

    int jend = 2 * qt + 1;                 // causal
    int jlen = (len - 1) >> 6;             // padding
    if (jlen < jend) jend = jlen;

    const int lc  = tid & 31;              // d-pair / key-pair column
    const int lr0 = tid >> 5;              // 0..7

    for (int j = 0; j <= jend; j++) {
        const int k0 = j * 64;
        __syncthreads();
        // ---- load K tile [64 keys][32 u32] ----
        {
            const uint32_t* Kh = g_Khi + (headbase + k0) * 32;
            const uint32_t* Kl = g_Klo + (headbase + k0) * 32;
            const uint32_t* Vh = g_Vhi + (headbase + k0) * 32;
            const uint32_t* Vl = g_Vlo + (headbase + k0) * 32;
            unsigned short* shv = (unsigned short*)sVhi;
            unsigned short* slv = (unsigned short*)sVlo;
#pragma unroll
            for (int i = 0; i < 8; i++) {
                int key = lr0 + i * 8;
                sKhi[key * KSTR + lc] = Kh[key * 32 + lc];
                sKlo[key * KSTR + lc] = Kl[key * 32 + lc];
                // V transpose: u32 = d pair (2lc, 2lc+1) of key -> sV[d][key]
                uint32_t hv = Vh[key * 32 + lc];
                uint32_t lv = Vl[key * 32 + lc];
                int d0 = lc * 2;
                shv[d0 * (2 * KSTR) + key]       = (unsigned short)(hv & 0xFFFF);
                shv[(d0 + 1) * (2 * KSTR) + key] = (unsigned short)(hv >> 16);
                slv[d0 * (2 * KSTR) + key]       = (unsigned short)(lv & 0xFFFF);
                slv[(d0 + 1) * (2 * KSTR) + key] = (unsigned short)(lv >> 16);
            }
        }
        __syncthreads();

        if (k0 > q0w + 15) continue;       // whole tile causally masked for this warp

        // ---- S = Q K^T : 8 n-tiles x 4 k-steps x 3 terms ----
        float s[8][4];
#pragma unroll
        for (int jn = 0; jn < 8; jn++)
#pragma unroll
            for (int c = 0; c < 4; c++) s[jn][c] = 0.f;
#pragma unroll
        for (int jn = 0; jn < 8; jn++) {
            const int nrow = (jn * 8 + grp) * KSTR;
#pragma unroll
            for (int sk = 0; sk < 4; sk++) {
                const int off = nrow + sk * 8 + qk;
                uint32_t bh[2], bl[2];
                bh[0] = sKhi[off]; bh[1] = sKhi[off + 4];
                bl[0] = sKlo[off]; bl[1] = sKlo[off + 4];
                mma_bf16(s[jn], aQhi[sk], bh);
                mma_bf16(s[jn], aQlo[sk], bh);
                mma_bf16(s[jn], aQhi[sk], bl);
            }
        }

        // ---- mask + online softmax (rows grp, grp+8; lanes qk share row) ----
        float mx0 = -INFINITY, mx1 = -INFINITY;
#pragma unroll
        for (int jn = 0; jn < 8; jn++) {
#pragma unroll
            for (int c = 0; c < 4; c++) {
                int kk = k0 + jn * 8 + qk * 2 + (c & 1);
                int qq = (c < 2) ? qrow0 : qrow1;
                float sv = s[jn][c] * invs;
                if (kk > qq || kk >= len) sv = -INFINITY;
                s[jn][c] = sv;
                if (c < 2) mx0 = fmaxf(mx0, sv); else mx1 = fmaxf(mx1, sv);
            }
        }
        mx0 = fmaxf(mx0, __shfl_xor_sync(0xffffffffu, mx0, 1));
        mx0 = fmaxf(mx0, __shfl_xor_sync(0xffffffffu, mx0, 2));
        mx1 = fmaxf(mx1, __shfl_xor_sync(0xffffffffu, mx1, 1));
        mx1 = fmaxf(mx1, __shfl_xor_sync(0xffffffffu, mx1, 2));

        float mn0 = fmaxf(m0, mx0), mn1 = fmaxf(m1, mx1);
        float a0 = __expf(m0 - mn0), a1 = __expf(m1 - mn1);
        m0 = mn0; m1 = mn1;

        float rs0 = 0.f, rs1 = 0.f;
#pragma unroll
        for (int jn = 0; jn < 8; jn++) {
            float p0 = __expf(s[jn][0] - mn0);
            float p1 = __expf(s[jn][1] - mn0);
            float p2 = __expf(s[jn][2] - mn1);
            float p3 = __expf(s[jn][3] - mn1);
            s[jn][0] = p0; s[jn][1] = p1; s[jn][2] = p2; s[jn][3] = p3;
            rs0 += p0 + p1; rs1 += p2 + p3;
        }
        rs0 += __shfl_xor_sync(0xffffffffu, rs0, 1);
        rs0 += __shfl_xor_sync(0xffffffffu, rs0, 2);
        rs1 += __shfl_xor_sync(0xffffffffu, rs1, 1);
        rs1 += __shfl_xor_sync(0xffffffffu, rs1, 2);
        l0 = l0 * a0 + rs0;
        l1 = l1 * a1 + rs1;

#pragma unroll
        for (int jn = 0; jn < 8; jn++) {
            oacc[jn][0] *= a0; oacc[jn][1] *= a0;
            oacc[jn][2] *= a1; oacc[jn][3] *= a1;
        }

        // ---- P fragments (accumulator layout == A layout), then O += P V ----
        uint32_t aPhi[4][4], aPlo[4][4];
#pragma unroll
        for (int sk = 0; sk < 4; sk++) {
            split2(s[2 * sk][0],     s[2 * sk][1],     aPhi[sk][0], aPlo[sk][0]);
            split2(s[2 * sk][2],     s[2 * sk][3],     aPhi[sk][1], aPlo[sk][1]);
            split2(s[2 * sk + 1][0], s[2 * sk + 1][1], aPhi[sk][2], aPlo[sk][2]);
            split2(s[2 * sk + 1][2], s[2 * sk + 1][3], aPhi[sk][3], aPlo[sk][3]);
        }
#pragma unroll
        for (int jn = 0; jn < 8; jn++) {
            const int nrow = (jn * 8 + grp) * KSTR;
#pragma unroll
            for (int sk = 0; sk < 4; sk++) {
                const int off = nrow + sk * 8 + qk;
                uint32_t bh[2], bl[2];
                bh[0] = sVhi[off]; bh[1] = sVhi[off + 4];
                bl[0] = sVlo[off]; bl[1] = sVlo[off + 4];
                mma_bf16(oacc[jn], aPhi[sk], bh);
                mma_bf16(oacc[jn], aPlo[sk], bh);
                mma_bf16(oacc[jn], aPhi[sk], bl);
            }
        }
    }

    // ---- epilogue: O / l -> out[n][q][h*64 + d] ----
    float il0 = 1.f / l0, il1 = 1.f / l1;
#pragma unroll
    for (int jn = 0; jn < 8; jn++) {
        int col = hh * HD + jn * 8 + qk * 2;
        float2 v0 = make_float2(oacc[jn][0] * il0, oacc[jn][1] * il0);
        float2 v1 = make_float2(oacc[jn][2] * il1, oacc[jn][3] * il1);
        *(float2*)&out[((size_t)nb * SEQ + qrow0) * DM + col] = v0;
        *(float2*)&out[((size_t)nb * SEQ + qrow1) * DM + col] = v1;
    }
}

// ---------------- launch ----------------
extern "C" void kernel_launch(void* const* d_in, const int* in_sizes, int n_in,
                              void* d_out, int out_size)
{
    const float* query = (const float*)d_in[0];
    const float* key   = (const float*)d_in[1];
    const float* Wq    = (const float*)d_in[2];
    const float* Wk    = (const float*)d_in[3];
    const float* Wv    = (const float*)d_in[4];
    const unsigned char* mask = (const unsigned char*)d_in[5];
    const unsigned char* pm   = (const unsigned char*)d_in[6];
    float* out = (float*)d_out;

    len_kernel<<<1, 256>>>(mask, pm);

    dim3 pg(DM / PBN, (N_B * SEQ) / PBM);      // (8, 32)
    proj_mma<<<pg, 256>>>(query, Wq, 0);
    proj_mma<<<pg, 256>>>(key,   Wk, 1);
    proj_mma<<<pg, 256>>>(key,   Wv, 2);

    attn_mma<<<dim3(SEQ / 128, H, N_B), 256>>>(out);
}